// round 13
// baseline (speedup 1.0000x reference)
#include <cuda_runtime.h>

// TemporalPSPGate: state_t = ALPHA*state_{t-1} + x_t ; out_t = x_t * sigmoid(state_t)
// x [T=16, B=16, H=8, N=256, D=64] fp32. 256 MiB logical traffic per launch.
// R5:  depth-2 prefetch + single-MUFU tanh sigmoid.
// R10: st.global.wt stores (no dirty L2 at replay boundary).
// R11: depth-3 prefetch FAILED -> back to depth-2.
// R12: 256-bit accesses (sm_103a ld.global.nc.v8.f32 / st.global.wt.v8.f32).
//      8 floats/thread/t: halves LDG/STG count per byte; each warp request is
//      1KB contiguous (8 sectors, one DRAM page) -> better request efficiency
//      at the memory controller. Same skeleton otherwise.

#define TT 16
#define SPATIAL (16 * 8 * 256 * 64)          // 2,097,152 floats per timestep
#define NTHREADS (SPATIAL / 8)               // 262,144 v8 lanes

struct F8 { float v[8]; };

__device__ __forceinline__ float tanh_approx(float s) {
    float r;
    asm("tanh.approx.f32 %0, %1;" : "=f"(r) : "f"(s));
    return r;
}

__device__ __forceinline__ F8 ldg_v8(const float* p) {
    F8 r;
    asm volatile("ld.global.nc.v8.f32 {%0,%1,%2,%3,%4,%5,%6,%7}, [%8];"
                 : "=f"(r.v[0]), "=f"(r.v[1]), "=f"(r.v[2]), "=f"(r.v[3]),
                   "=f"(r.v[4]), "=f"(r.v[5]), "=f"(r.v[6]), "=f"(r.v[7])
                 : "l"(p));
    return r;
}

__device__ __forceinline__ void stg_v8_wt(float* p, const F8& a) {
    asm volatile("st.global.wt.v8.f32 [%0], {%1,%2,%3,%4,%5,%6,%7,%8};"
                 :: "l"(p),
                    "f"(a.v[0]), "f"(a.v[1]), "f"(a.v[2]), "f"(a.v[3]),
                    "f"(a.v[4]), "f"(a.v[5]), "f"(a.v[6]), "f"(a.v[7])
                 : "memory");
}

__global__ __launch_bounds__(128) void psp_gate_kernel(
    const float* __restrict__ x, float* __restrict__ out)
{
    const int gid = blockIdx.x * blockDim.x + threadIdx.x;   // 0 .. NTHREADS-1
    const float alpha = 0.60653065971263342360f;             // exp(-1/2)

    const float* xp = x + (long long)gid * 8;
    float*       op = out + (long long)gid * 8;

    float st[8];
    #pragma unroll
    for (int i = 0; i < 8; i++) st[i] = 0.f;

    // Depth-2 rotating prefetch: always 2 independent 256-bit LDG in flight.
    F8 buf0 = ldg_v8(xp);
    F8 buf1 = ldg_v8(xp + SPATIAL);
    xp += 2 * (long long)SPATIAL;

    #pragma unroll
    for (int t = 0; t < TT; t++) {
        F8 xv = (t & 1) ? buf1 : buf0;

        if (t + 2 < TT) {
            if (t & 1) buf1 = ldg_v8(xp);
            else       buf0 = ldg_v8(xp);
            xp += SPATIAL;
        }

        F8 ov;
        #pragma unroll
        for (int i = 0; i < 8; i++) {
            st[i] = fmaf(alpha, st[i], xv.v[i]);
            // sigmoid(s) = 0.5*tanh(0.5*s) + 0.5 ; out = x*sigmoid
            float hx = 0.5f * xv.v[i];
            ov.v[i] = fmaf(hx, tanh_approx(0.5f * st[i]), hx);
        }

        stg_v8_wt(op, ov);   // write-through: no dirty L2 at replay boundary
        op += SPATIAL;
    }
}

extern "C" void kernel_launch(void* const* d_in, const int* in_sizes, int n_in,
                              void* d_out, int out_size) {
    const float* x = (const float*)d_in[0];
    float* out = (float*)d_out;
    const int threads = 128;
    const int blocks = NTHREADS / threads;   // 2048
    psp_gate_kernel<<<blocks, threads>>>(x, out);
}

// round 14
// speedup vs baseline: 1.0894x; 1.0894x over previous
#include <cuda_runtime.h>

// TemporalPSPGate: state_t = ALPHA*state_{t-1} + x_t ; out_t = x_t * sigmoid(state_t)
// x [T=16, B=16, H=8, N=256, D=64] fp32. 256 MiB logical traffic per launch.
// R5:  2048x256 float4, depth-2 prefetch, single-MUFU tanh sigmoid.
// R10: st.global.wt stores (no dirty L2 at replay boundary). Best: 45.5us.
// R11 (depth-3), R12 (v8/256-bit) both FAILED -> reverted. L2 residency plays
//     (R8/R9) inert/harmful. At 5.86 TB/s on 50/50 r/w mix we are near the
//     practical HBM turnaround floor.
// R13: last untested knob in the winning structure: LOAD eviction policy.
//      All prior rounds used .cs (evict-first) loads; default evict_normal
//      (__ldg) never run. Plain LDG.E.CI + .wt stores; everything else = R10.

#define TT 16
#define SPATIAL4 ((16 * 8 * 256 * 64) / 4)   // 524,288 float4 lanes

__device__ __forceinline__ float tanh_approx(float s) {
    float r;
    asm("tanh.approx.f32 %0, %1;" : "=f"(r) : "f"(s));
    return r;
}

__device__ __forceinline__ void stg_wt(float4* p, float4 v) {
    asm volatile("st.global.wt.v4.f32 [%0], {%1,%2,%3,%4};"
                 :: "l"(p), "f"(v.x), "f"(v.y), "f"(v.z), "f"(v.w)
                 : "memory");
}

__global__ __launch_bounds__(256, 6) void psp_gate_kernel(
    const float4* __restrict__ x, float4* __restrict__ out)
{
    const int gid = blockIdx.x * blockDim.x + threadIdx.x;
    const float alpha = 0.60653065971263342360f;   // exp(-1/2)

    const float4* xp = x + gid;
    float4*       op = out + gid;

    float4 st = make_float4(0.f, 0.f, 0.f, 0.f);

    // Depth-2 rotating prefetch: always 2 independent LDG.128 in flight.
    // Default eviction policy (no .cs) — the one load variant never benched.
    float4 buf0 = __ldg(xp);
    float4 buf1 = __ldg(xp + SPATIAL4);
    xp += 2 * (long long)SPATIAL4;

    #pragma unroll
    for (int t = 0; t < TT; t++) {
        float4 xv = (t & 1) ? buf1 : buf0;

        if (t + 2 < TT) {
            if (t & 1) buf1 = __ldg(xp);
            else       buf0 = __ldg(xp);
            xp += SPATIAL4;
        }

        st.x = fmaf(alpha, st.x, xv.x);
        st.y = fmaf(alpha, st.y, xv.y);
        st.z = fmaf(alpha, st.z, xv.z);
        st.w = fmaf(alpha, st.w, xv.w);

        // sigmoid(s) = 0.5*tanh(0.5*s) + 0.5 ; out = x*sigmoid
        float hx = 0.5f * xv.x;
        float hy = 0.5f * xv.y;
        float hz = 0.5f * xv.z;
        float hw = 0.5f * xv.w;

        float4 ov;
        ov.x = fmaf(hx, tanh_approx(0.5f * st.x), hx);
        ov.y = fmaf(hy, tanh_approx(0.5f * st.y), hy);
        ov.z = fmaf(hz, tanh_approx(0.5f * st.z), hz);
        ov.w = fmaf(hw, tanh_approx(0.5f * st.w), hw);

        stg_wt(op, ov);    // write-through: no dirty L2 lines at replay boundary
        op += SPATIAL4;
    }
}

extern "C" void kernel_launch(void* const* d_in, const int* in_sizes, int n_in,
                              void* d_out, int out_size) {
    const float4* x = (const float4*)d_in[0];
    float4* out = (float4*)d_out;
    const int threads = 256;
    const int blocks = SPATIAL4 / threads;   // 2048
    psp_gate_kernel<<<blocks, threads>>>(x, out);
}

// round 15
// speedup vs baseline: 1.0986x; 1.0085x over previous
#include <cuda_runtime.h>

// TemporalPSPGate: state_t = ALPHA*state_{t-1} + x_t ; out_t = x_t * sigmoid(state_t)
// x [T=16, B=16, H=8, N=256, D=64] fp32. 256 MiB logical traffic per launch.
// R5/R10 plateau: 45.5us harness / 36.2 ncu / 74% DRAM. Ruled out: MLP depth,
// occupancy shape, wave tail, L2 residency (both polarities), 256-bit ops,
// load eviction policy.
// R14: attack HBM read<->write TURNAROUND — the only unexplored axis. All prior
//      variants interleaved LDG/STG per-t (worst-case 50/50 fine-grain mix).
//      Now: batch ALL 16 loads per thread (pure 8KB read burst per warp),
//      compute scan in registers, then batch ALL 16 .wt stores (pure write
//      burst). Coarser r/w phases at the MC = fewer bus turnarounds.
//      Cost: 64-reg x buffer -> ~80 regs, 3 CTAs/SM (37.5% occ) — harmless,
//      in-flight bytes (24 warps x 8KB) >> Little's-law need (~13KB/SM).

#define TT 16
#define SPATIAL4 ((16 * 8 * 256 * 64) / 4)   // 524,288 float4 lanes

__device__ __forceinline__ float tanh_approx(float s) {
    float r;
    asm("tanh.approx.f32 %0, %1;" : "=f"(r) : "f"(s));
    return r;
}

__device__ __forceinline__ void stg_wt(float4* p, float4 v) {
    asm volatile("st.global.wt.v4.f32 [%0], {%1,%2,%3,%4};"
                 :: "l"(p), "f"(v.x), "f"(v.y), "f"(v.z), "f"(v.w)
                 : "memory");
}

__global__ __launch_bounds__(256, 3) void psp_gate_kernel(
    const float4* __restrict__ x, float4* __restrict__ out)
{
    const int gid = blockIdx.x * blockDim.x + threadIdx.x;
    const float alpha = 0.60653065971263342360f;   // exp(-1/2)

    const float4* xp = x + gid;

    // Phase 1: 16 back-to-back independent LDG.128 — pure read burst.
    float4 xv[TT];
    #pragma unroll
    for (int t = 0; t < TT; t++)
        xv[t] = __ldcs(xp + (long long)t * SPATIAL4);

    // Phase 2: scan + gate in registers, overwriting xv[] with the output
    // (compute for t=0 begins while later loads are still in flight).
    float4 st = make_float4(0.f, 0.f, 0.f, 0.f);
    #pragma unroll
    for (int t = 0; t < TT; t++) {
        st.x = fmaf(alpha, st.x, xv[t].x);
        st.y = fmaf(alpha, st.y, xv[t].y);
        st.z = fmaf(alpha, st.z, xv[t].z);
        st.w = fmaf(alpha, st.w, xv[t].w);

        float hx = 0.5f * xv[t].x;
        float hy = 0.5f * xv[t].y;
        float hz = 0.5f * xv[t].z;
        float hw = 0.5f * xv[t].w;

        xv[t].x = fmaf(hx, tanh_approx(0.5f * st.x), hx);
        xv[t].y = fmaf(hy, tanh_approx(0.5f * st.y), hy);
        xv[t].z = fmaf(hz, tanh_approx(0.5f * st.z), hz);
        xv[t].w = fmaf(hw, tanh_approx(0.5f * st.w), hw);
    }

    // Phase 3: 16 back-to-back STG.128.wt — pure write burst, no dirty L2.
    float4* op = out + gid;
    #pragma unroll
    for (int t = 0; t < TT; t++)
        stg_wt(op + (long long)t * SPATIAL4, xv[t]);
}

extern "C" void kernel_launch(void* const* d_in, const int* in_sizes, int n_in,
                              void* d_out, int out_size) {
    const float4* x = (const float4*)d_in[0];
    float4* out = (float4*)d_out;
    const int threads = 256;
    const int blocks = SPATIAL4 / threads;   // 2048
    psp_gate_kernel<<<blocks, threads>>>(x, out);
}

// round 16
// speedup vs baseline: 1.1064x; 1.0071x over previous
#include <cuda_runtime.h>

// TemporalPSPGate: state_t = ALPHA*state_{t-1} + x_t ; out_t = x_t * sigmoid(state_t)
// x [T=16, B=16, H=8, N=256, D=64] fp32. 256 MiB logical traffic per launch.
// Plateau ~45.5us harness over 8 variants; near mixed-stream HBM floor.
// R14 (16-deep bursts, 80 regs, 31% occ) ~= R10 (fine interleave, 40 regs, 64%).
// R15: midpoint — TWO half-bursts of 8: (8x LDG burst -> scan -> 8x STG.wt
//      burst) x2. Keeps r/w burst grouping at only ~56 regs -> ~50% occ; both
//      knobs near their individually-best values. Plus ld.global.nc.L2::256B
//      prefetch hint on the sequential read stream (untested, free).

#define TT 16
#define HT 8                                  // half-burst depth
#define SPATIAL4 ((16 * 8 * 256 * 64) / 4)    // 524,288 float4 lanes

__device__ __forceinline__ float tanh_approx(float s) {
    float r;
    asm("tanh.approx.f32 %0, %1;" : "=f"(r) : "f"(s));
    return r;
}

__device__ __forceinline__ float4 ldg_pf256(const float4* p) {
    float4 v;
    asm volatile("ld.global.nc.L2::256B.v4.f32 {%0,%1,%2,%3}, [%4];"
                 : "=f"(v.x), "=f"(v.y), "=f"(v.z), "=f"(v.w)
                 : "l"(p));
    return v;
}

__device__ __forceinline__ void stg_wt(float4* p, float4 v) {
    asm volatile("st.global.wt.v4.f32 [%0], {%1,%2,%3,%4};"
                 :: "l"(p), "f"(v.x), "f"(v.y), "f"(v.z), "f"(v.w)
                 : "memory");
}

__global__ __launch_bounds__(256, 4) void psp_gate_kernel(
    const float4* __restrict__ x, float4* __restrict__ out)
{
    const int gid = blockIdx.x * blockDim.x + threadIdx.x;
    const float alpha = 0.60653065971263342360f;   // exp(-1/2)

    float4 st = make_float4(0.f, 0.f, 0.f, 0.f);

    #pragma unroll
    for (int h = 0; h < 2; h++) {
        const float4* xp = x   + (long long)(h * HT) * SPATIAL4 + gid;
        float4*       op = out + (long long)(h * HT) * SPATIAL4 + gid;

        // Read burst: 8 back-to-back independent LDG.128 (+L2 256B prefetch).
        float4 xv[HT];
        #pragma unroll
        for (int t = 0; t < HT; t++)
            xv[t] = ldg_pf256(xp + (long long)t * SPATIAL4);

        // Scan + gate in registers; output overwrites the buffer.
        #pragma unroll
        for (int t = 0; t < HT; t++) {
            st.x = fmaf(alpha, st.x, xv[t].x);
            st.y = fmaf(alpha, st.y, xv[t].y);
            st.z = fmaf(alpha, st.z, xv[t].z);
            st.w = fmaf(alpha, st.w, xv[t].w);

            float hx = 0.5f * xv[t].x;
            float hy = 0.5f * xv[t].y;
            float hz = 0.5f * xv[t].z;
            float hw = 0.5f * xv[t].w;

            xv[t].x = fmaf(hx, tanh_approx(0.5f * st.x), hx);
            xv[t].y = fmaf(hy, tanh_approx(0.5f * st.y), hy);
            xv[t].z = fmaf(hz, tanh_approx(0.5f * st.z), hz);
            xv[t].w = fmaf(hw, tanh_approx(0.5f * st.w), hw);
        }

        // Write burst: 8 back-to-back STG.128.wt (no dirty L2 at replay end).
        #pragma unroll
        for (int t = 0; t < HT; t++)
            stg_wt(op + (long long)t * SPATIAL4, xv[t]);
    }
}

extern "C" void kernel_launch(void* const* d_in, const int* in_sizes, int n_in,
                              void* d_out, int out_size) {
    const float4* x = (const float4*)d_in[0];
    float4* out = (float4*)d_out;
    const int threads = 256;
    const int blocks = SPATIAL4 / threads;   // 2048
    psp_gate_kernel<<<blocks, threads>>>(x, out);
}

// round 17
// speedup vs baseline: 1.1072x; 1.0007x over previous
#include <cuda_runtime.h>

// TemporalPSPGate: state_t = ALPHA*state_{t-1} + x_t ; out_t = x_t * sigmoid(state_t)
// x [T=16, B=16, H=8, N=256, D=64] fp32. 256 MiB logical traffic per launch.
// R15 (best, 45.1us): two half-bursts of 8 (8x LDG+L2::256B burst -> scan ->
//      8x STG.wt burst), 64 regs, block 256 -> 4 CTAs/SM (41.9% occ).
// R16: same structure, block 128: 8192 regs/CTA -> 8 CTAs/SM fills the RF
//      exactly -> 66% occ. Combines the proven burst structure with the
//      proven-good occupancy level (never had simultaneously before).

#define TT 16
#define HT 8                                  // half-burst depth
#define SPATIAL4 ((16 * 8 * 256 * 64) / 4)    // 524,288 float4 lanes

__device__ __forceinline__ float tanh_approx(float s) {
    float r;
    asm("tanh.approx.f32 %0, %1;" : "=f"(r) : "f"(s));
    return r;
}

__device__ __forceinline__ float4 ldg_pf256(const float4* p) {
    float4 v;
    asm volatile("ld.global.nc.L2::256B.v4.f32 {%0,%1,%2,%3}, [%4];"
                 : "=f"(v.x), "=f"(v.y), "=f"(v.z), "=f"(v.w)
                 : "l"(p));
    return v;
}

__device__ __forceinline__ void stg_wt(float4* p, float4 v) {
    asm volatile("st.global.wt.v4.f32 [%0], {%1,%2,%3,%4};"
                 :: "l"(p), "f"(v.x), "f"(v.y), "f"(v.z), "f"(v.w)
                 : "memory");
}

__global__ __launch_bounds__(128, 8) void psp_gate_kernel(
    const float4* __restrict__ x, float4* __restrict__ out)
{
    const int gid = blockIdx.x * blockDim.x + threadIdx.x;
    const float alpha = 0.60653065971263342360f;   // exp(-1/2)

    float4 st = make_float4(0.f, 0.f, 0.f, 0.f);

    #pragma unroll
    for (int h = 0; h < 2; h++) {
        const float4* xp = x   + (long long)(h * HT) * SPATIAL4 + gid;
        float4*       op = out + (long long)(h * HT) * SPATIAL4 + gid;

        // Read burst: 8 back-to-back independent LDG.128 (+L2 256B prefetch).
        float4 xv[HT];
        #pragma unroll
        for (int t = 0; t < HT; t++)
            xv[t] = ldg_pf256(xp + (long long)t * SPATIAL4);

        // Scan + gate in registers; output overwrites the buffer.
        #pragma unroll
        for (int t = 0; t < HT; t++) {
            st.x = fmaf(alpha, st.x, xv[t].x);
            st.y = fmaf(alpha, st.y, xv[t].y);
            st.z = fmaf(alpha, st.z, xv[t].z);
            st.w = fmaf(alpha, st.w, xv[t].w);

            float hx = 0.5f * xv[t].x;
            float hy = 0.5f * xv[t].y;
            float hz = 0.5f * xv[t].z;
            float hw = 0.5f * xv[t].w;

            xv[t].x = fmaf(hx, tanh_approx(0.5f * st.x), hx);
            xv[t].y = fmaf(hy, tanh_approx(0.5f * st.y), hy);
            xv[t].z = fmaf(hz, tanh_approx(0.5f * st.z), hz);
            xv[t].w = fmaf(hw, tanh_approx(0.5f * st.w), hw);
        }

        // Write burst: 8 back-to-back STG.128.wt (no dirty L2 at replay end).
        #pragma unroll
        for (int t = 0; t < HT; t++)
            stg_wt(op + (long long)t * SPATIAL4, xv[t]);
    }
}

extern "C" void kernel_launch(void* const* d_in, const int* in_sizes, int n_in,
                              void* d_out, int out_size) {
    const float4* x = (const float4*)d_in[0];
    float4* out = (float4*)d_out;
    const int threads = 128;
    const int blocks = SPATIAL4 / threads;   // 4096
    psp_gate_kernel<<<blocks, threads>>>(x, out);
}